// round 17
// baseline (speedup 1.0000x reference)
#include <cuda_runtime.h>
#include <cuda_bf16.h>

#define P_TOT  61440
#define NTHR   256
#define TPI    960
#define NCTA   5760

/* smem map (bytes) */
#define AHI     0        /* 64 rows x 512B (256 bf16 cols, swizzled) */
#define ALO     32768
#define WB0     65536    /* 16KB weight chunk buf */
#define WB1     81920
#define SBO     98304    /* 960 float biases */
#define SMEM_TOT 102144

/* bf16 weights, hi/lo split, k16-chunk layout:
   chunk c of layer: [hi: N rows x 32B swz | lo: same], chunk_bytes = N*64 */
static __device__ __align__(16) __nv_bfloat16 g_w[344064];

__global__ void prep_kernel(const float* __restrict__ w0, const float* __restrict__ w1,
                            const float* __restrict__ w2, const float* __restrict__ w3,
                            const float* __restrict__ w4, const float* __restrict__ w5)
{
    const int K[6]    = {65,64,64,256,256,256};
    const int N[6]    = {64,64,256,256,256,64};
    const int KC[6]   = {4,4,4,16,16,16};          /* L0: t folded into bias, K=64 */
    const int GOFF[6] = {0,8192,16384,49152,180224,311296};   /* elems */
    int l = blockIdx.y;
    const float* w = (l==0)?w0:(l==1)?w1:(l==2)?w2:(l==3)?w3:(l==4)?w4:w5;
    int Nl = N[l], Kl = K[l];
    int total = KC[l]*Nl*16;
    for (int idx = blockIdx.x*blockDim.x + threadIdx.x; idx < total; idx += gridDim.x*blockDim.x){
        int kin = idx & 15;
        int n   = (idx >> 4) % Nl;
        int c   = idx / (16*Nl);
        int k   = c*16 + kin;
        float v = (k < Kl) ? w[n*Kl + k] : 0.0f;
        __nv_bfloat16 h  = __float2bfloat16(v);
        __nv_bfloat16 lo = __float2bfloat16(v - __bfloat162float(h));
        int eoff = n*16 + ((((kin>>3) ^ ((n>>2)&1))) << 3) + (kin & 7);
        int base = GOFF[l] + c*(Nl*32);
        g_w[base + eoff]          = h;
        g_w[base + Nl*16 + eoff]  = lo;
    }
}

/* ---------------- helpers ---------------- */
__device__ __forceinline__ unsigned s2u(const void* p){
    unsigned a;
    asm("{ .reg .u64 t; cvta.to.shared.u64 t, %1; cvt.u32.u64 %0, t; }" : "=r"(a) : "l"(p));
    return a;
}
__device__ __forceinline__ void cp16(unsigned dst, const void* src){
    asm volatile("cp.async.cg.shared.global [%0], [%1], 16;" :: "r"(dst), "l"(src));
}
__device__ __forceinline__ void cp_commit(){ asm volatile("cp.async.commit_group;"); }
__device__ __forceinline__ void cp_wait0(){ asm volatile("cp.async.wait_group 0;"); }
__device__ __forceinline__ void stage(unsigned dst, const char* src, int bytes, int tid){
    for (int i = tid*16; i < bytes; i += NTHR*16) cp16(dst + i, src + i);
}
__device__ __forceinline__ void ldmx4(unsigned* r, unsigned addr){
    asm volatile("ldmatrix.sync.aligned.m8n8.x4.shared.b16 {%0,%1,%2,%3}, [%4];"
        : "=r"(r[0]), "=r"(r[1]), "=r"(r[2]), "=r"(r[3]) : "r"(addr));
}
__device__ __forceinline__ void mma_bf16(float* c, const unsigned* a, unsigned b0, unsigned b1){
    asm volatile("mma.sync.aligned.m16n8k16.row.col.f32.bf16.bf16.f32 "
        "{%0,%1,%2,%3}, {%4,%5,%6,%7}, {%8,%9}, {%0,%1,%2,%3};"
        : "+f"(c[0]), "+f"(c[1]), "+f"(c[2]), "+f"(c[3])
        : "r"(a[0]), "r"(a[1]), "r"(a[2]), "r"(a[3]), "r"(b0), "r"(b1));
}
__device__ __forceinline__ unsigned pack_bf2(float hi_val, float lo_val){
    unsigned r;  /* d.lo = lo_val, d.hi = hi_val */
    asm("cvt.rn.bf16x2.f32 %0, %1, %2;" : "=r"(r) : "f"(hi_val), "f"(lo_val));
    return r;
}
__device__ __forceinline__ float bflo(unsigned u){ return __bfloat162float(((__nv_bfloat162*)&u)->x); }
__device__ __forceinline__ float bfhi(unsigned u){ return __bfloat162float(((__nv_bfloat162*)&u)->y); }

/* sin(30*acc + b30) on the FMA pipe: fma range reduction + degree-11 odd poly.
   |r| <= pi/2, abs err < 1e-7. b30 = 30*bias (pre-scaled in smem). */
__device__ __forceinline__ float sin30(float acc, float b30){
    float u  = fmaf(acc, 30.0f, b30);
    int   k  = __float2int_rn(u * 0.3183098861837907f);
    float kf = (float)k;
    float r  = fmaf(kf, -3.1415927410125732f, u);     /* u - k*PI_HI (exact in fma) */
    r        = fmaf(kf,  8.742277657347586e-8f, r);   /* - k*PI_LO */
    float z  = r*r;
    float p  = fmaf(-2.50521084e-08f, z,  2.75573192e-06f);
    p        = fmaf(p, z, -1.98412698e-04f);
    p        = fmaf(p, z,  8.33333333e-03f);
    p        = fmaf(p, z, -1.66666666e-01f);
    float s  = fmaf(p, z*r, r);
    return __int_as_float(__float_as_int(s) ^ ((k & 1) << 31));
}

/* one layer: A in smem (AHI/ALO, 64 rows x 512B), in-place epilogue update.
   kc = number of k16 chunks, Nl = output cols, chunk staged per k-step. */
template<int NF, bool LAST>
__device__ __forceinline__ void lay(unsigned smb, char* smp,
    const char* gw, int kc, int Nl, const float* sbL,
    const char* gnext, int nbytes, int& buf,
    int wm, int wn, int lane, int tid, float* outp)
{
    const int gid   = lane >> 2, tig = lane & 3;
    const int row_a = (lane & 7) + ((lane >> 3) & 1)*8;
    const int ca    = lane >> 4;
    const int n_off = (lane & 7) + (lane >> 4)*8;
    const int cb    = (lane >> 3) & 1;
    const int cbytes = Nl*64;

    float acc[2][NF][4];
#pragma unroll
    for (int i = 0; i < 2; i++)
#pragma unroll
        for (int j = 0; j < NF; j++)
#pragma unroll
            for (int q = 0; q < 4; q++) acc[i][j][q] = 0.0f;

    int cur = buf;
    for (int c = 0; c < kc; c++){
        cp_wait0();
        __syncthreads();
        if (c + 1 < kc){
            stage(smb + (cur ? WB0 : WB1), gw + (size_t)(c+1)*cbytes, cbytes, tid);
            cp_commit();
        }
        unsigned wb  = smb + (cur ? WB1 : WB0);
        unsigned wlo = wb + (unsigned)(Nl*32);

        unsigned ah[2][4], al[2][4];
#pragma unroll
        for (int mt = 0; mt < 2; mt++){
            int row = wm*32 + mt*16 + row_a;
            unsigned off = (unsigned)(row*512) + ((((unsigned)(2*c + ca) ^ (unsigned)(row & 7))) << 4);
            ldmx4(ah[mt], smb + AHI + off);
            ldmx4(al[mt], smb + ALO + off);
        }
#pragma unroll
        for (int np = 0; np < NF/2; np++){
            int nl = wn*(8*NF) + np*16 + n_off;
            unsigned off = (unsigned)(nl*32) + ((((unsigned)cb ^ (unsigned)((nl >> 2) & 1))) << 4);
            unsigned bh[4], bl[4];
            ldmx4(bh, wb + off);
            ldmx4(bl, wlo + off);
#pragma unroll
            for (int mt = 0; mt < 2; mt++){
                mma_bf16(acc[mt][2*np],   ah[mt], bh[0], bh[1]);
                mma_bf16(acc[mt][2*np],   al[mt], bh[0], bh[1]);
                mma_bf16(acc[mt][2*np],   ah[mt], bl[0], bl[1]);
                mma_bf16(acc[mt][2*np+1], ah[mt], bh[2], bh[3]);
                mma_bf16(acc[mt][2*np+1], al[mt], bh[2], bh[3]);
                mma_bf16(acc[mt][2*np+1], ah[mt], bl[2], bl[3]);
            }
        }
        cur ^= 1;
    }
    buf = cur;
    __syncthreads();                 /* all A reads done before in-place update */
    if (gnext){
        stage(smb + (cur ? WB1 : WB0), gnext, nbytes, tid);
        cp_commit();
    }

#pragma unroll
    for (int mt = 0; mt < 2; mt++){
#pragma unroll
        for (int j = 0; j < NF; j++){
            int n  = wn*(8*NF) + j*8 + 2*tig;
            int r0 = wm*32 + mt*16 + gid;
            if (!LAST){
                float bx = sbL[n], by = sbL[n+1];
                float v0 = sin30(acc[mt][j][0], bx);
                float v1 = sin30(acc[mt][j][1], by);
                float v2 = sin30(acc[mt][j][2], bx);
                float v3 = sin30(acc[mt][j][3], by);
                unsigned h0 = pack_bf2(v1, v0);
                unsigned l0 = pack_bf2(v1 - bfhi(h0), v0 - bflo(h0));
                unsigned h1 = pack_bf2(v3, v2);
                unsigned l1 = pack_bf2(v3 - bfhi(h1), v2 - bflo(h1));
                unsigned off0 = (unsigned)(r0*512)     + ((((unsigned)(n>>3) ^ (unsigned)(r0 & 7))) << 4)     + (unsigned)((n & 7)*2);
                unsigned off1 = (unsigned)((r0+8)*512) + ((((unsigned)(n>>3) ^ (unsigned)((r0+8) & 7))) << 4) + (unsigned)((n & 7)*2);
                *(unsigned*)(smp + AHI + off0) = h0;
                *(unsigned*)(smp + ALO + off0) = l0;
                *(unsigned*)(smp + AHI + off1) = h1;
                *(unsigned*)(smp + ALO + off1) = l1;
            } else {
                outp[(size_t)n*P_TOT     + r0]     = acc[mt][j][0] + sbL[n];
                outp[(size_t)(n+1)*P_TOT + r0]     = acc[mt][j][1] + sbL[n+1];
                outp[(size_t)n*P_TOT     + r0 + 8] = acc[mt][j][2] + sbL[n];
                outp[(size_t)(n+1)*P_TOT + r0 + 8] = acc[mt][j][3] + sbL[n+1];
            }
        }
    }
}

__global__ void __launch_bounds__(NTHR, 2)
mlp_mma2_kernel(const float* __restrict__ feat, const float* __restrict__ times,
                const float* __restrict__ w0,
                const float* __restrict__ b0, const float* __restrict__ b1,
                const float* __restrict__ b2, const float* __restrict__ b3,
                const float* __restrict__ b4, const float* __restrict__ b5,
                float* __restrict__ out)
{
    extern __shared__ char smp[];
    float* sb = (float*)(smp + SBO);
    const unsigned smb = s2u(smp);
    const int tid  = threadIdx.x;
    const int wid  = tid >> 5;
    const int lane = tid & 31;
    const int wm   = wid & 1;       /* 2 M-groups (32 rows each) */
    const int wn   = wid >> 1;      /* 4 N-groups */

    const int tile = blockIdx.x;
    const int img  = tile / TPI;
    const int p0   = (tile - img*TPI) * 64;
    const int cidx = img >> 1, bidx = img & 1;
    const float tval = times[cidx];

    /* biases pre-scaled by 30 (except last layer); t folded into L0 bias */
    if (tid < 64){
        sb[tid]     = 30.0f*fmaf(tval, w0[tid*65 + 64], b0[tid]);
        sb[64+tid]  = 30.0f*b1[tid];
        sb[896+tid] = b5[tid];
    }
    for (int i = tid; i < 256; i += NTHR){
        sb[128+i] = 30.0f*b2[i];
        sb[384+i] = 30.0f*b3[i];
        sb[640+i] = 30.0f*b4[i];
    }

    /* stage L0 chunk0 (4KB) */
    stage(smb + WB0, (const char*)g_w, 4096, tid);
    cp_commit();

    /* build A0 bf16 hi/lo: 64 rows x 64 feat channels */
    {
        const float* fb = feat + (size_t)(bidx*64)*P_TOT + p0;
        for (int idx = tid; idx < 4096; idx += NTHR){
            int r = idx & 63, ch = idx >> 6;
            float v = fb[(size_t)ch*P_TOT + r];
            __nv_bfloat16 h  = __float2bfloat16(v);
            __nv_bfloat16 lo = __float2bfloat16(v - __bfloat162float(h));
            unsigned off = (unsigned)(r*512) + ((((unsigned)(ch>>3) ^ (unsigned)(r&7))) << 4) + (unsigned)((ch & 7)*2);
            *(unsigned short*)(smp + AHI + off) = *(unsigned short*)&h;
            *(unsigned short*)(smp + ALO + off) = *(unsigned short*)&lo;
        }
    }

    float* outp = out + (size_t)img*64*P_TOT + p0;
    const char* gw = (const char*)g_w;   /* byte offsets = elem offsets * 2 */
    int buf = 0;

    lay<2,false>(smb, smp, gw +      0,  4,  64, sb +   0, gw +  16384,  4096, buf, wm, wn, lane, tid, outp);
    lay<2,false>(smb, smp, gw +  16384,  4,  64, sb +  64, gw +  32768, 16384, buf, wm, wn, lane, tid, outp);
    lay<8,false>(smb, smp, gw +  32768,  4, 256, sb + 128, gw +  98304, 16384, buf, wm, wn, lane, tid, outp);
    lay<8,false>(smb, smp, gw +  98304, 16, 256, sb + 384, gw + 360448, 16384, buf, wm, wn, lane, tid, outp);
    lay<8,false>(smb, smp, gw + 360448, 16, 256, sb + 640, gw + 622592,  4096, buf, wm, wn, lane, tid, outp);
    lay<2,true >(smb, smp, gw + 622592, 16,  64, sb + 896, (const char*)0, 0,  buf, wm, wn, lane, tid, outp);
}

extern "C" void kernel_launch(void* const* d_in, const int* in_sizes, int n_in,
                              void* d_out, int out_size)
{
    const float* feat  = (const float*)d_in[0];
    const float* times = (const float*)d_in[1];
    const float* w0 = (const float*)d_in[2];
    const float* b0 = (const float*)d_in[3];
    const float* w1 = (const float*)d_in[4];
    const float* b1 = (const float*)d_in[5];
    const float* w2 = (const float*)d_in[6];
    const float* b2 = (const float*)d_in[7];
    const float* w3 = (const float*)d_in[8];
    const float* b3 = (const float*)d_in[9];
    const float* w4 = (const float*)d_in[10];
    const float* b4 = (const float*)d_in[11];
    const float* w5 = (const float*)d_in[12];
    const float* b5 = (const float*)d_in[13];
    float* out = (float*)d_out;

    cudaFuncSetAttribute(mlp_mma2_kernel, cudaFuncAttributeMaxDynamicSharedMemorySize, SMEM_TOT);

    prep_kernel<<<dim3(64, 6), 256>>>(w0, w1, w2, w3, w4, w5);
    mlp_mma2_kernel<<<NCTA, NTHR, SMEM_TOT>>>(feat, times, w0, b0, b1, b2, b3, b4, b5, out);
}